// round 9
// baseline (speedup 1.0000x reference)
#include <cuda_runtime.h>

// Problem constants (fixed shapes per reference)
#define KROWS 1025
#define F     8192
#define NCHUNK 256
#define RPC   4            // rows per chunk = 1024/256

// Device scratch (no allocations in kernel_launch)
__device__ float g_partial[NCHUNK * F];   // 8 MB
__device__ float g_scale[F];
__device__ unsigned g_cnt[8];             // per column-group arrival counters

// Kernel 1: partial |x| column sums + fused finalize.
// Grid (8, 256): blockIdx.x = 1024-column group, blockIdx.y = 4-row chunk.
// The LAST block to finish within a column group folds all 256 partials and
// computes scale / center row / ext diagonal for its 1024 columns.
__global__ void __launch_bounds__(256) relu_z_reduce(
    const float* __restrict__ x,
    const float* __restrict__ lambdas,
    float* __restrict__ out)
{
    const int tid   = threadIdx.x;
    const int cx    = blockIdx.x;          // 0..7
    const int chunk = blockIdx.y;          // 0..255
    const int c4    = (cx << 8) + tid;     // float4 column 0..2047
    const size_t st = F / 4;

    // 4 independent loads — small enough to stay fully in flight.
    const float4* p = (const float4*)(x + (size_t)(1 + chunk * RPC) * F) + c4;
    float4 v0 = p[0 * st];
    float4 v1 = p[1 * st];
    float4 v2 = p[2 * st];
    float4 v3 = p[3 * st];

    float4 s;
    s.x = (fabsf(v0.x) + fabsf(v1.x)) + (fabsf(v2.x) + fabsf(v3.x));
    s.y = (fabsf(v0.y) + fabsf(v1.y)) + (fabsf(v2.y) + fabsf(v3.y));
    s.z = (fabsf(v0.z) + fabsf(v1.z)) + (fabsf(v2.z) + fabsf(v3.z));
    s.w = (fabsf(v0.w) + fabsf(v1.w)) + (fabsf(v2.w) + fabsf(v3.w));
    ((float4*)(g_partial + chunk * F))[c4] = s;

    // ── Election: last-arriving block of this column group finalizes.
    __threadfence();
    __shared__ int s_elected;
    if (tid == 0) {
        unsigned old = atomicAdd(&g_cnt[cx], 1u);
        s_elected = (old == NCHUNK - 1);
        if (s_elected) g_cnt[cx] = 0;      // reset for next graph replay
    }
    __syncthreads();
    if (!s_elected) return;
    __threadfence();                       // order fold reads after arrivals

    // Fold 256 partials for float4 column c4 (all L2-resident).
    float4 acc = make_float4(0.f, 0.f, 0.f, 0.f);
    const float4* gp = (const float4*)g_partial;
    #pragma unroll 16
    for (int c = 0; c < NCHUNK; ++c) {
        float4 t = gp[(size_t)c * st + c4];
        acc.x += t.x; acc.y += t.y; acc.z += t.z; acc.w += t.w;
    }

    float4 ctr = ((const float4*)x)[c4];        // x[0], 4 features
    float4 lam = ((const float4*)lambdas)[c4];

    float4 scale4, center4;
    float hf[4];
    {
        const float* ab = (const float*)&acc;
        const float* ct = (const float*)&ctr;
        const float* lm = (const float*)&lam;
        float* sc = (float*)&scale4;
        float* ce = (float*)&center4;
        #pragma unroll
        for (int k = 0; k < 4; ++k) {
            float l = ct[k] - ab[k];
            float u = ct[k] + ab[k];
            float pos   = (l > 0.0f) ? 1.0f : 0.0f;
            float cross = ((u > 0.0f) && (l < 0.0f)) ? 1.0f : 0.0f;
            float d     = fmaxf(-l * lm[k], u * (1.0f - lm[k]));
            sc[k] = pos + cross * lm[k];
            hf[k] = 0.5f * cross * d;
            ce[k] = sc[k] * ct[k] + hf[k];
        }
    }

    ((float4*)g_scale)[c4] = scale4;
    ((float4*)out)[c4]     = center4;           // center row

    // Ext diagonal: feature f = 4*c4+k lives in float4 slot (f>>2) == c4.
    #pragma unroll
    for (int k = 0; k < 4; ++k) {
        int f = (c4 << 2) + k;
        float4 dv = make_float4(0.f, 0.f, 0.f, 0.f);
        ((float*)&dv)[k] = hf[k];
        ((float4*)(out + (size_t)(KROWS + f) * F))[c4] = dv;
    }
}

// Kernel 2: ALL remaining stores in one launch.
// Unit = half a row = 1024 float4 = 256 threads x 4 float4.
//   blocks [0, 2048)     : body rows 1..1024, out = scale * x (x is L2-hot)
//   blocks [2048, 18432) : ext rows, streaming zeros, skip diagonal float4
__global__ void __launch_bounds__(256) relu_z_store_all(
    const float* __restrict__ x, float* __restrict__ out)
{
    const int b   = blockIdx.x;
    const int tid = threadIdx.x;

    if (b < 2048) {
        int r  = 1 + (b >> 1);
        int c0 = ((b & 1) << 10) + tid;
        const float4* xs = (const float4*)(x + (size_t)r * F);
        const float4* sc = (const float4*)g_scale;
        float4* os = (float4*)(out + (size_t)r * F);
        #pragma unroll
        for (int j = 0; j < 4; ++j) {
            int i = c0 + (j << 8);
            float4 v = xs[i];
            float4 s = sc[i];
            float4 o;
            o.x = s.x * v.x;
            o.y = s.y * v.y;
            o.z = s.z * v.z;
            o.w = s.w * v.w;
            __stcs(&os[i], o);             // out never re-read: bypass L2 fill
        }
    } else {
        int e     = b - 2048;
        int row   = e >> 1;
        int diag4 = row >> 2;              // float4 slot owned by relu_z_reduce
        int c0    = ((e & 1) << 10) + tid;
        float4* os = (float4*)(out + (size_t)(KROWS + row) * F);
        const float4 z = make_float4(0.f, 0.f, 0.f, 0.f);

        // diag4 falls in this half-row iff its high bits match; only the
        // thread whose lane matches can collide.
        bool hasDiag = ((diag4 >> 10) == (e & 1)) && ((diag4 & 255) == tid);
        if (!hasDiag) {
            #pragma unroll
            for (int j = 0; j < 4; ++j) __stcs(&os[c0 + (j << 8)], z);
        } else {
            #pragma unroll
            for (int j = 0; j < 4; ++j) {
                int i = c0 + (j << 8);
                if (i != diag4) __stcs(&os[i], z);
            }
        }
    }
}

extern "C" void kernel_launch(void* const* d_in, const int* in_sizes, int n_in,
                              void* d_out, int out_size) {
    const float* x       = (const float*)d_in[0];
    const float* lambdas = (const float*)d_in[1];
    float* out           = (float*)d_out;

    // 1) Reduction + fused finalize (scale, center row, ext diagonal)
    {
        dim3 grid(8, NCHUNK);              // 2048 blocks
        relu_z_reduce<<<grid, 256>>>(x, lambdas, out);
    }
    // 2) Everything else: body rows + ext zeros, one launch
    relu_z_store_all<<<2048 + 16384, 256>>>(x, out);
}

// round 10
// speedup vs baseline: 1.2314x; 1.2314x over previous
#include <cuda_runtime.h>

// Problem constants (fixed shapes per reference)
#define KROWS 1025
#define F     8192
#define NCHUNK 256
#define RPC   4            // rows per chunk = 1024/256

// Device scratch (no allocations in kernel_launch)
__device__ float g_partial[NCHUNK * F];   // 8 MB
__device__ float g_scale[F];

// Kernel 1: partial |x| column sums, 4 rows per block.
// Grid (8, 256) = 2048 blocks, 524K threads: 4 independent float4 loads per
// thread stay fully in flight within the granted register budget.
__global__ void __launch_bounds__(256) relu_z_partial_abs(
    const float* __restrict__ x)
{
    const int tid   = threadIdx.x;
    const int c4    = (blockIdx.x << 8) + tid;   // float4 column 0..2047
    const int chunk = blockIdx.y;                // 0..255
    const size_t st = F / 4;

    const float4* p = (const float4*)(x + (size_t)(1 + chunk * RPC) * F) + c4;
    float4 v0 = p[0 * st];
    float4 v1 = p[1 * st];
    float4 v2 = p[2 * st];
    float4 v3 = p[3 * st];

    float4 s;
    s.x = (fabsf(v0.x) + fabsf(v1.x)) + (fabsf(v2.x) + fabsf(v3.x));
    s.y = (fabsf(v0.y) + fabsf(v1.y)) + (fabsf(v2.y) + fabsf(v3.y));
    s.z = (fabsf(v0.z) + fabsf(v1.z)) + (fabsf(v2.z) + fabsf(v3.z));
    s.w = (fabsf(v0.w) + fabsf(v1.w)) + (fabsf(v2.w) + fabsf(v3.w));
    ((float4*)(g_partial + chunk * F))[c4] = s;
}

// Kernel 2: fold the 256 partials (L2-resident) -> scale; write center row
// and the ext diagonal float4s. 32 blocks x 256 threads = full-width fold.
__global__ void __launch_bounds__(256) relu_z_finalize(
    const float* __restrict__ x,
    const float* __restrict__ lambdas,
    float* __restrict__ out)
{
    int f = blockIdx.x * blockDim.x + threadIdx.x;   // 0..F-1
    float abssum = 0.0f;
    #pragma unroll 16
    for (int c = 0; c < NCHUNK; ++c) abssum += g_partial[c * F + f];

    float ctr = x[f];                 // x[0][f]
    float l = ctr - abssum;
    float u = ctr + abssum;
    float lam = lambdas[f];

    float pos   = (l > 0.0f) ? 1.0f : 0.0f;
    float cross = ((u > 0.0f) && (l < 0.0f)) ? 1.0f : 0.0f;
    float d     = fmaxf(-l * lam, u * (1.0f - lam));
    float scale = pos + cross * lam;
    float half  = 0.5f * cross * d;

    g_scale[f] = scale;
    out[f] = scale * ctr + half;      // center row

    // diagonal float4 of the ext block (store_all skips this slot)
    float4 dv = make_float4(0.f, 0.f, 0.f, 0.f);
    ((float*)&dv)[f & 3] = half;
    ((float4*)(out + (size_t)(KROWS + f) * F))[f >> 2] = dv;
}

// Kernel 3: ALL remaining stores in one launch.
// Unit = half a row = 1024 float4 = 256 threads x 4 float4.
//   blocks [0, 2048)     : body rows 1..1024, out = scale * x (x is L2-hot)
//   blocks [2048, 18432) : ext rows, streaming zeros, skip diagonal float4
__global__ void __launch_bounds__(256) relu_z_store_all(
    const float* __restrict__ x, float* __restrict__ out)
{
    const int b   = blockIdx.x;
    const int tid = threadIdx.x;

    if (b < 2048) {
        int r  = 1 + (b >> 1);
        int c0 = ((b & 1) << 10) + tid;
        const float4* xs = (const float4*)(x + (size_t)r * F);
        const float4* sc = (const float4*)g_scale;
        float4* os = (float4*)(out + (size_t)r * F);
        #pragma unroll
        for (int j = 0; j < 4; ++j) {
            int i = c0 + (j << 8);
            float4 v = xs[i];
            float4 s = sc[i];
            float4 o;
            o.x = s.x * v.x;
            o.y = s.y * v.y;
            o.z = s.z * v.z;
            o.w = s.w * v.w;
            __stcs(&os[i], o);             // out never re-read: bypass L2 fill
        }
    } else {
        int e     = b - 2048;
        int row   = e >> 1;
        int diag4 = row >> 2;              // float4 slot owned by finalize
        int c0    = ((e & 1) << 10) + tid;
        float4* os = (float4*)(out + (size_t)(KROWS + row) * F);
        const float4 z = make_float4(0.f, 0.f, 0.f, 0.f);

        // diag4 lies in this half-row iff its bit-10 matches; only the thread
        // whose low 8 bits match can collide -> single hoisted branch.
        bool hasDiag = ((diag4 >> 10) == (e & 1)) && ((diag4 & 255) == tid);
        if (!hasDiag) {
            #pragma unroll
            for (int j = 0; j < 4; ++j) __stcs(&os[c0 + (j << 8)], z);
        } else {
            #pragma unroll
            for (int j = 0; j < 4; ++j) {
                int i = c0 + (j << 8);
                if (i != diag4) __stcs(&os[i], z);
            }
        }
    }
}

extern "C" void kernel_launch(void* const* d_in, const int* in_sizes, int n_in,
                              void* d_out, int out_size) {
    const float* x       = (const float*)d_in[0];
    const float* lambdas = (const float*)d_in[1];
    float* out           = (float*)d_out;

    // 1) Partial abs-sums: 8 col-groups x 256 row-chunks = 2048 blocks
    {
        dim3 grid(8, NCHUNK);
        relu_z_partial_abs<<<grid, 256>>>(x);
    }
    // 2) Finalize: scale, center row, ext diagonal (32 blocks)
    relu_z_finalize<<<F / 256, 256>>>(x, lambdas, out);
    // 3) Everything else: body rows + ext zeros, one launch
    relu_z_store_all<<<2048 + 16384, 256>>>(x, out);
}